// round 15
// baseline (speedup 1.0000x reference)
#include <cuda_runtime.h>
#include <cuda_fp16.h>
#include <math.h>
#include <stdint.h>

// Problem dims
#define BB   64
#define TT   512
#define INS  512
#define HH   1024
#define G4   4096          // 4*HH
#define TB   (TT*BB)       // 32768

// Recurrence kernel config: 2 independent batch groups x 64 CTAs.
// CTA owns 16 units (64 gate rows) for its group's 32 batch rows.
#define NCTA_REC 128
#define HS       (HH+8)    // padded smem row stride (fp16) for the w_hh tile
#define REC_THREADS 512    // 16 warps = seg8 x nh2; per warp M=32, N=32, K=128
#define PB       (32*65)   // partial buffer: 32 batch rows x 64 cols (pad 65)

// ---------------------------------------------------------------------------
// Scratch (device globals; no allocation allowed)
// ---------------------------------------------------------------------------
__device__ __align__(128) __half d_xb[TB*INS];         // x transposed to [t,b,k], fp16
__device__ __align__(128) __half d_wih0[G4*INS];
__device__ __align__(128) __half d_whh0[G4*HH];
__device__ __align__(128) __half d_wih1[G4*HH];
__device__ __align__(128) __half d_whh1[G4*HH];
__device__ __align__(128) float  d_gx[(size_t)TB*G4];  // 512MB, reused by both layers
__device__ __align__(128) __half d_h1[(size_t)TB*HH];  // layer0 outputs (row-major history)
__device__ __align__(128) __half d_h2[(size_t)TB*HH];  // layer1 outputs (row-major history)
// recurrent h in MMA fragment order, per group: [group2][ping2][4096 uint4]
__device__ __align__(128) __half d_hfrag[2*2*32*HH];
// one flag per CTA, padded to one 128B L2 line each; flag index = g*64+cg
__device__ __align__(128) unsigned d_flags[NCTA_REC * 32];
#define FLAG(i) d_flags[(i) << 5]

// ---------------------------------------------------------------------------
// Helpers
// ---------------------------------------------------------------------------
__device__ __forceinline__ void mma16816(float* d, const uint32_t* a, uint32_t b0, uint32_t b1) {
    asm volatile(
        "mma.sync.aligned.m16n8k16.row.col.f32.f16.f16.f32 "
        "{%0,%1,%2,%3},{%4,%5,%6,%7},{%8,%9},{%0,%1,%2,%3};\n"
        : "+f"(d[0]), "+f"(d[1]), "+f"(d[2]), "+f"(d[3])
        : "r"(a[0]), "r"(a[1]), "r"(a[2]), "r"(a[3]), "r"(b0), "r"(b1));
}

__device__ __forceinline__ void ldsm_x4(uint32_t& r0, uint32_t& r1, uint32_t& r2, uint32_t& r3,
                                        uint32_t addr) {
    asm volatile("ldmatrix.sync.aligned.m8n8.x4.shared.b16 {%0,%1,%2,%3}, [%4];"
                 : "=r"(r0), "=r"(r1), "=r"(r2), "=r"(r3) : "r"(addr));
}

__device__ __forceinline__ void cp16(uint32_t dst, const void* src) {
    asm volatile("cp.async.cg.shared.global [%0], [%1], 16;" :: "r"(dst), "l"(src));
}
#define CP_COMMIT()  asm volatile("cp.async.commit_group;")
#define CP_WAIT(n)   asm volatile("cp.async.wait_group %0;" :: "n"(n))

__device__ __forceinline__ unsigned ld_acq(const unsigned* p) {
    unsigned v;
    asm volatile("ld.global.acquire.gpu.b32 %0, [%1];" : "=r"(v) : "l"(p));
    return v;
}
__device__ __forceinline__ void st_rel(unsigned* p, unsigned v) {
    asm volatile("st.global.release.gpu.b32 [%0], %1;" :: "l"(p), "r"(v));
}

// L2-only 128b load (bypasses L1 -> no stale lines across ping-pong reuse)
__device__ __forceinline__ uint4 ldcg128(const uint4* p) {
    uint4 v;
    asm volatile("ld.global.cg.v4.u32 {%0,%1,%2,%3}, [%4];"
                 : "=r"(v.x), "=r"(v.y), "=r"(v.z), "=r"(v.w) : "l"(p));
    return v;
}

// Fast gate math (MUFU-based). Gate args bounded; ~1e-6 rel err << fp16 noise.
__device__ __forceinline__ float sigf(float x)   { return 1.0f / (1.0f + __expf(-x)); }
__device__ __forceinline__ float tanhfast(float x) {
    return 1.0f - 2.0f / (__expf(2.0f * x) + 1.0f);
}

// ---------------------------------------------------------------------------
// Conversions
// ---------------------------------------------------------------------------
__global__ void k_conv_x(const float* __restrict__ x, __half* __restrict__ xb) {
    int i = blockIdx.x * blockDim.x + threadIdx.x;   // over 2^24 elements
    int k = i & (INS - 1);
    int t = (i >> 9) & (TT - 1);
    int b = i >> 18;
    xb[(size_t)(t * BB + b) * INS + k] = __float2half(x[i]);
}

__global__ void k_conv_w(const float* __restrict__ s0, __half* __restrict__ o0, int n0,
                         const float* __restrict__ s1, __half* __restrict__ o1, int n1,
                         const float* __restrict__ s2, __half* __restrict__ o2, int n2,
                         const float* __restrict__ s3, __half* __restrict__ o3, int n3) {
    int i = blockIdx.x * blockDim.x + threadIdx.x;
    if (i < n0) o0[i] = __float2half(s0[i]);
    if (i < n1) o1[i] = __float2half(s1[i]);
    if (i < n2) o2[i] = __float2half(s2[i]);
    if (i < n3) o3[i] = __float2half(s3[i]);
}

// ---------------------------------------------------------------------------
// Batched GEMM (unchanged)
// ---------------------------------------------------------------------------
#define BM 128
#define BN 128
#define BK 64
#define KP 72   // padded k stride

__global__ __launch_bounds__(256) void k_gemm_bias(
    const __half* __restrict__ A,
    const __half* __restrict__ Bw,
    const float* __restrict__ bias1,
    const float* __restrict__ bias2,
    float* __restrict__ C, int M, int N, int K)
{
    extern __shared__ __half gsm_h[];
    __half* sAp = gsm_h;
    __half* sBp = gsm_h + 2 * BM * KP;

    const int bm = blockIdx.x * BM;
    const int bn = blockIdx.y * BN;
    const int tid  = threadIdx.x;
    const int w    = tid >> 5, lane = tid & 31;
    const int gid  = lane >> 2, lg = lane & 3;
    const int wm   = w >> 2, wn = w & 3;
    const int m0   = wm * 64, n0 = wn * 32;

    const int lrow = tid >> 3, lc = (tid & 7) * 8;

    const int lr8 = lane & 7, lsel = lane >> 3;
    const int a_row = lr8 + ((lsel & 1) << 3);
    const int a_col = (lsel >> 1) << 3;
    const int b_row = ((lsel >> 1) << 3) + lr8;
    const int b_col = (lsel & 1) << 3;

    uint32_t aBase0 = (uint32_t)__cvta_generic_to_shared(sAp);
    uint32_t bBase0 = (uint32_t)__cvta_generic_to_shared(sBp);
    const uint32_t bufA = (uint32_t)(BM * KP * 2);
    const uint32_t bufB = (uint32_t)(BN * KP * 2);

    float acc[4][4][4];
    #pragma unroll
    for (int mt = 0; mt < 4; mt++)
        #pragma unroll
        for (int nt = 0; nt < 4; nt++)
            #pragma unroll
            for (int r = 0; r < 4; r++) acc[mt][nt][r] = 0.0f;

    const int nc = K / BK;

    #pragma unroll
    for (int i = 0; i < 4; i++) {
        int row = lrow + i * 32;
        cp16(aBase0 + (uint32_t)((row * KP + lc) * 2), &A[(size_t)(bm + row) * K + lc]);
        cp16(bBase0 + (uint32_t)((row * KP + lc) * 2), &Bw[(size_t)(bn + row) * K + lc]);
    }
    CP_COMMIT();

    for (int c = 0; c < nc; c++) {
        if (c + 1 < nc) {
            int kc = (c + 1) * BK;
            uint32_t dA = aBase0 + ((c + 1) & 1) * bufA;
            uint32_t dB = bBase0 + ((c + 1) & 1) * bufB;
            #pragma unroll
            for (int i = 0; i < 4; i++) {
                int row = lrow + i * 32;
                cp16(dA + (uint32_t)((row * KP + lc) * 2), &A[(size_t)(bm + row) * K + kc + lc]);
                cp16(dB + (uint32_t)((row * KP + lc) * 2), &Bw[(size_t)(bn + row) * K + kc + lc]);
            }
            CP_COMMIT();
            CP_WAIT(1);
        } else {
            CP_WAIT(0);
        }
        __syncthreads();

        uint32_t aB = aBase0 + (c & 1) * bufA;
        uint32_t bB = bBase0 + (c & 1) * bufB;

        #pragma unroll
        for (int ks = 0; ks < BK / 16; ks++) {
            const int kb = ks * 16;
            uint32_t a[4][4];
            #pragma unroll
            for (int mt = 0; mt < 4; mt++) {
                uint32_t addr = aB + (uint32_t)(((m0 + mt * 16 + a_row) * KP + kb + a_col) * 2);
                ldsm_x4(a[mt][0], a[mt][1], a[mt][2], a[mt][3], addr);
            }
            uint32_t b[4][2];
            #pragma unroll
            for (int np = 0; np < 2; np++) {
                uint32_t addr = bB + (uint32_t)(((n0 + np * 16 + b_row) * KP + kb + b_col) * 2);
                uint32_t r0, r1, r2, r3;
                ldsm_x4(r0, r1, r2, r3, addr);
                b[np * 2][0] = r0;     b[np * 2][1] = r1;
                b[np * 2 + 1][0] = r2; b[np * 2 + 1][1] = r3;
            }
            #pragma unroll
            for (int nt = 0; nt < 4; nt++)
                #pragma unroll
                for (int mt = 0; mt < 4; mt++)
                    mma16816(acc[mt][nt], a[mt], b[nt][0], b[nt][1]);
        }
        __syncthreads();
    }

    #pragma unroll
    for (int mt = 0; mt < 4; mt++) {
        #pragma unroll
        for (int nt = 0; nt < 4; nt++) {
            int gm1 = bm + m0 + mt * 16 + gid;
            int gn  = bn + n0 + nt * 8 + lg * 2;
            float bi0 = bias1[gn] + bias2[gn];
            float bi1 = bias1[gn + 1] + bias2[gn + 1];
            float2 v0 = make_float2(acc[mt][nt][0] + bi0, acc[mt][nt][1] + bi1);
            float2 v1 = make_float2(acc[mt][nt][2] + bi0, acc[mt][nt][3] + bi1);
            *reinterpret_cast<float2*>(&C[(size_t)gm1 * N + gn]) = v0;
            *reinterpret_cast<float2*>(&C[(size_t)(gm1 + 8) * N + gn]) = v1;
        }
    }
}

// ---------------------------------------------------------------------------
// Persistent LSTM recurrence — batch-split, no-redundancy-LDSM edition.
// 2 independent groups of 64 CTAs; group g handles batch rows [g*32,+32);
// CTA cg owns 16 units (64 gate rows), w_hh slice resident in smem.
// 16 warps = seg8 x nh2: each warp owns a UNIQUE 32-row x 128-col w_hh slice
// (B read exactly once per step -> LDSM traffic halved vs R13) and handles
// all M=32 batch rows itself (two A-fragment sets per ks, straight from L2
// via ld.global.cg.v4 in fragment order; A reads 2x, cheap at L2=5%).
// Tail: 8 K-segment partials -> ONE sync -> 512-wide pointwise sums 8
// partials + gx, register c state, h stored in fragment order -> sync ->
// release-store publish (group-local flags). 3 syncs/step.
// ---------------------------------------------------------------------------
__global__ __launch_bounds__(REC_THREADS) void k_lstm_rec(
    const float* __restrict__ gx,           // [T*B, 4096]
    const __half* __restrict__ whh,         // [4096, 1024] fp16
    __half* __restrict__ hall)              // [T*B, H] fp16 (row-major history)
{
    extern __shared__ __align__(16) char smem[];
    __half* wsm = reinterpret_cast<__half*>(smem);          // 64 * HS (w_hh slice)
    float* pbuf = reinterpret_cast<float*>(wsm + 64 * HS);  // 8 * PB partials

    const int tid = threadIdx.x;
    const int cta = blockIdx.x;
    const int g   = cta >> 6;          // batch group
    const int cg  = cta & 63;          // CTA within group
    const int j0  = cg * 16;           // first owned unit
    const int lane = tid & 31, w = tid >> 5;
    const int gid = lane >> 2, lg = lane & 3;
    const int seg = w >> 1;            // K segment 0..7 (128 cols each)
    const int nh  = w & 1;             // N half 0..1 (32 of 64 gate rows)

    const uint32_t wsm_u = (uint32_t)__cvta_generic_to_shared(wsm);

    // LDSM lane addressing (B operand): 2 x4-loads cover this warp's
    // 32 gate rows x 16 cols per ks.
    const int lr8 = lane & 7, lsel = lane >> 3;
    const int b_row = ((lsel >> 1) << 3) + lr8;
    const int b_col = (lsel & 1) << 3;
    uint32_t bAddr[2];
    #pragma unroll
    for (int q = 0; q < 2; q++)
        bAddr[q] = wsm_u + (uint32_t)(((nh * 32 + q * 16 + b_row) * HS + seg * 128 + b_col) * 2);

    // A-fragment source: group-local buffer of 4096 uint4.
    // uint4 index for (wA, ks): (wA*8 + ks)*32 + lane, wA = seg*2 + mt.
    const int hfw_base = seg * 512 + lane;   // + ks*32 (mt0), +256 (mt1)
    const uint4* fragbase = reinterpret_cast<const uint4*>(d_hfrag);

    // Load this CTA's 64 gate rows of w_hh into smem (once).
    // smem row rc = gate*16 + jj  <->  w_hh row  gate*HH + j0 + jj
    #pragma unroll
    for (int i = 0; i < 16; i++) {
        int idx = tid + i * REC_THREADS;    // 0..8191
        int row = idx >> 7, c8 = idx & 127;
        int grow = (row >> 4) * HH + j0 + (row & 15);
        *reinterpret_cast<uint4*>(&wsm[row * HS + c8 * 8]) =
            *reinterpret_cast<const uint4*>(&whh[(size_t)grow * HH + c8 * 8]);
    }

    // pointwise ownership: thread -> (b_local = tid>>4, jj = tid&15)
    const int pw_b = tid >> 4, pw_j = tid & 15;
    float creg = 0.0f;
    // producer fragment offset (within group-ping buffer); CTA-fixed seg/ks
    size_t fragoff;
    {
        int mtp = pw_b >> 4, gidp = pw_b & 7, rhalf = (pw_b >> 3) & 1;
        int segp = cg >> 3, ksp = cg & 7;
        int khalf = pw_j >> 3, lgp = (pw_j & 7) >> 1, odd = pw_j & 1;
        int wAp = segp * 2 + mtp;
        int lanep = gidp * 4 + lgp;
        int regp = rhalf + 2 * khalf;
        fragoff = ((size_t)((wAp * 8 + ksp) * 32 + lanep)) * 8 + regp * 2 + odd;
    }

    // flags: group-local. warp w polls flags g*64 + (w*4 + lane) for lane<4
    const int fidx = g * 64 + w * 4 + (lane & 3);
    unsigned basef = 0;
    if (lane < 4) basef = ld_acq(&FLAG(fidx));
    unsigned base0;
    {
        __shared__ unsigned sb;
        if (tid == 0) sb = ld_acq(&FLAG(g * 64 + cg));
        __syncthreads();
        base0 = sb;
    }

    for (int t = 0; t < TT; t++) {
        // gx prefetch: this thread's 4 gate inputs (independent of h(t))
        float gxv[4];
        {
            const float* gp = gx + ((size_t)(t * BB) + g * 32 + pw_b) * G4 + j0 + pw_j;
            #pragma unroll
            for (int gt = 0; gt < 4; gt++) gxv[gt] = gp[gt * HH];
        }

        float acc[2][4][4];    // [mt][nt][r]
        #pragma unroll
        for (int mt = 0; mt < 2; mt++)
            #pragma unroll
            for (int nt = 0; nt < 4; nt++)
                #pragma unroll
                for (int r = 0; r < 4; r++) acc[mt][nt][r] = 0.0f;

        if (t > 0) {
            if (lane < 4) {
                unsigned target = basef + (unsigned)t;
                while ((int)(ld_acq(&FLAG(fidx)) - target) < 0) __nanosleep(32);
            }
            __syncthreads();   // sync 1: all 64 producers observed CTA-wide

            const uint4* hfw = fragbase + ((size_t)(g * 2 + (t & 1))) * 4096 + hfw_base;

            // A-fragments (both m-tiles) from L2, double-buffered across ks
            uint4 af[2][2];
            af[0][0] = ldcg128(hfw);
            af[0][1] = ldcg128(hfw + 256);

            #pragma unroll
            for (int ks = 0; ks < 8; ks++) {
                if (ks < 7) {
                    af[(ks + 1) & 1][0] = ldcg128(hfw + (ks + 1) * 32);
                    af[(ks + 1) & 1][1] = ldcg128(hfw + 256 + (ks + 1) * 32);
                }
                const uint32_t koff = (uint32_t)(ks * 32);
                uint32_t b0, b1, b2, b3;
                ldsm_x4(b0, b1, b2, b3, bAddr[0] + koff);
                #pragma unroll
                for (int mt = 0; mt < 2; mt++) {
                    const uint32_t* a = reinterpret_cast<const uint32_t*>(&af[ks & 1][mt]);
                    mma16816(acc[mt][0], a, b0, b1);
                    mma16816(acc[mt][1], a, b2, b3);
                }
                ldsm_x4(b0, b1, b2, b3, bAddr[1] + koff);
                #pragma unroll
                for (int mt = 0; mt < 2; mt++) {
                    const uint32_t* a = reinterpret_cast<const uint32_t*>(&af[ks & 1][mt]);
                    mma16816(acc[mt][2], a, b0, b1);
                    mma16816(acc[mt][3], a, b2, b3);
                }
            }
        }
        // t == 0: h == 0 -> acc stays 0.

        // write this warp's partials to its K-segment buffer (cols nh*32..+32)
        {
            float* pb = pbuf + seg * PB;
            #pragma unroll
            for (int mt = 0; mt < 2; mt++) {
                const int r0o = (mt * 16 + gid) * 65, r1o = (mt * 16 + gid + 8) * 65;
                #pragma unroll
                for (int nt = 0; nt < 4; nt++) {
                    int col = nh * 32 + nt * 8 + lg * 2;
                    pb[r0o + col]     = acc[mt][nt][0];  pb[r0o + col + 1] = acc[mt][nt][1];
                    pb[r1o + col]     = acc[mt][nt][2];  pb[r1o + col + 1] = acc[mt][nt][3];
                }
            }
        }
        __syncthreads();   // sync 2: partials visible

        // pointwise: sum 8 K-segment partials + gx for this (b_local, jj)
        unsigned short hb;
        {
            const int o = pw_b * 65 + pw_j;
            float v[4];
            #pragma unroll
            for (int gt = 0; gt < 4; gt++) {
                const int oo = o + gt * 16;
                float s = gxv[gt];
                #pragma unroll
                for (int sgi = 0; sgi < 8; sgi++) s += pbuf[sgi * PB + oo];
                v[gt] = s;
            }
            creg = sigf(v[1]) * creg + sigf(v[0]) * tanhfast(v[2]);
            float h = sigf(v[3]) * tanhfast(creg);
            hb = __half_as_ushort(__float2half(h));
            // store h(t+1) in fragment order for next-step consumers
            *reinterpret_cast<unsigned short*>(
                &d_hfrag[((size_t)(g * 2 + ((t + 1) & 1))) * (32 * HH) + fragoff]) = hb;
        }
        __syncthreads();   // sync 3: hfrag stores done CTA-wide

        if (tid == 0) {
            st_rel(&FLAG(g * 64 + cg), base0 + (unsigned)t + 1u);
        }

        // row-major history store off the critical path (later kernels only)
        *reinterpret_cast<unsigned short*>(
            &hall[((size_t)(t * BB) + g * 32 + pw_b) * HH + j0 + pw_j]) = hb;
    }
}

// ---------------------------------------------------------------------------
// Output projection (unchanged)
// ---------------------------------------------------------------------------
__global__ void k_out(const __half* __restrict__ h2,
                      const float* __restrict__ wout,
                      const float* __restrict__ bout,
                      float* __restrict__ out)
{
    int wg = (blockIdx.x * blockDim.x + threadIdx.x) >> 5;
    int lane = threadIdx.x & 31;
    if (wg >= TB) return;
    int t = wg >> 6;     // / BB
    int b = wg & 63;
    const __half* hp = h2 + (size_t)wg * HH;
    float sum = 0.0f;
    #pragma unroll
    for (int i = 0; i < 4; i++) {
        int k = i * 256 + lane * 8;
        uint4 v = *reinterpret_cast<const uint4*>(&hp[k]);
        const __half* pv = reinterpret_cast<const __half*>(&v);
        float4 w0 = *reinterpret_cast<const float4*>(&wout[k]);
        float4 w1 = *reinterpret_cast<const float4*>(&wout[k + 4]);
        sum += __half2float(pv[0]) * w0.x + __half2float(pv[1]) * w0.y
             + __half2float(pv[2]) * w0.z + __half2float(pv[3]) * w0.w
             + __half2float(pv[4]) * w1.x + __half2float(pv[5]) * w1.y
             + __half2float(pv[6]) * w1.z + __half2float(pv[7]) * w1.w;
    }
    #pragma unroll
    for (int off = 16; off; off >>= 1) sum += __shfl_xor_sync(0xffffffffu, sum, off);
    if (lane == 0) out[(size_t)b * TT + t] = sum + bout[0];
}

// ---------------------------------------------------------------------------
// Launch. Stream order keeps k_lstm_rec (layer 0) at our launch index 3 (the
// ncu capture slot).
// ---------------------------------------------------------------------------
extern "C" void kernel_launch(void* const* d_in, const int* in_sizes, int n_in,
                              void* d_out, int out_size)
{
    const float* x     = (const float*)d_in[0];
    const float* w_ih0 = (const float*)d_in[1];
    const float* w_hh0 = (const float*)d_in[2];
    const float* b_ih0 = (const float*)d_in[3];
    const float* b_hh0 = (const float*)d_in[4];
    const float* w_ih1 = (const float*)d_in[5];
    const float* w_hh1 = (const float*)d_in[6];
    const float* b_ih1 = (const float*)d_in[7];
    const float* b_hh1 = (const float*)d_in[8];
    const float* w_out = (const float*)d_in[9];
    const float* b_out = (const float*)d_in[10];
    float* out = (float*)d_out;

    void *p_xb, *p_wih0, *p_whh0, *p_wih1, *p_whh1, *p_gx, *p_h1, *p_h2;
    cudaGetSymbolAddress(&p_xb, d_xb);
    cudaGetSymbolAddress(&p_wih0, d_wih0);
    cudaGetSymbolAddress(&p_whh0, d_whh0);
    cudaGetSymbolAddress(&p_wih1, d_wih1);
    cudaGetSymbolAddress(&p_whh1, d_whh1);
    cudaGetSymbolAddress(&p_gx, d_gx);
    cudaGetSymbolAddress(&p_h1, d_h1);
    cudaGetSymbolAddress(&p_h2, d_h2);

    const int SMEM_REC  = 64 * HS * 2 + 8 * PB * 4;               // 198656 B
    const int SMEM_GEMM = (2 * BM * KP + 2 * BN * KP) * 2;        // 73728 B
    cudaFuncSetAttribute(k_lstm_rec, cudaFuncAttributeMaxDynamicSharedMemorySize, SMEM_REC);
    cudaFuncSetAttribute(k_gemm_bias, cudaFuncAttributeMaxDynamicSharedMemorySize, SMEM_GEMM);

    // idx 0: x conversion
    k_conv_x<<<(TB * INS) / 256, 256>>>(x, (__half*)p_xb);
    // idx 1: all weight conversions fused
    k_conv_w<<<(G4 * HH) / 256, 256>>>(w_ih0, (__half*)p_wih0, G4 * INS,
                                       w_hh0, (__half*)p_whh0, G4 * HH,
                                       w_ih1, (__half*)p_wih1, G4 * HH,
                                       w_hh1, (__half*)p_whh1, G4 * HH);

    dim3 gg(TB / BM, G4 / BN);

    // idx 2: gx0 = x @ w_ih0^T + biases
    k_gemm_bias<<<gg, 256, SMEM_GEMM>>>((__half*)p_xb, (__half*)p_wih0,
                                        b_ih0, b_hh0, (float*)p_gx, TB, G4, INS);
    // idx 3: layer-0 recurrence  (ncu capture target)
    k_lstm_rec<<<NCTA_REC, REC_THREADS, SMEM_REC>>>((float*)p_gx, (__half*)p_whh0,
                                                    (__half*)p_h1);

    // idx 4: gx1 = h1 @ w_ih1^T + biases ; idx 5: layer-1 recurrence
    k_gemm_bias<<<gg, 256, SMEM_GEMM>>>((__half*)p_h1, (__half*)p_wih1,
                                        b_ih1, b_hh1, (float*)p_gx, TB, G4, HH);
    k_lstm_rec<<<NCTA_REC, REC_THREADS, SMEM_REC>>>((float*)p_gx, (__half*)p_whh1,
                                                    (__half*)p_h2);

    // idx 6: output projection
    k_out<<<(TB * 32) / 256, 256>>>((__half*)p_h2, w_out, b_out, out);
}

// round 16
// speedup vs baseline: 1.0705x; 1.0705x over previous
#include <cuda_runtime.h>
#include <cuda_fp16.h>
#include <math.h>
#include <stdint.h>

// Problem dims
#define BB   64
#define TT   512
#define INS  512
#define HH   1024
#define G4   4096          // 4*HH
#define TB   (TT*BB)       // 32768

// Recurrence kernel config: 2 independent batch groups x 64 CTAs.
// CTA owns 16 units (64 gate rows) for its group's 32 batch rows.
#define NCTA_REC 128
#define HS       (HH+8)    // padded smem row stride (fp16) for the w_hh tile
#define REC_THREADS 512    // 16 warps: (kq4 x ng2) k-segments x mt2
#define PB       (32*65)   // partial buffer: 32 batch rows x 64 cols (pad 65)

// ---------------------------------------------------------------------------
// Scratch (device globals; no allocation allowed)
// ---------------------------------------------------------------------------
__device__ __align__(128) __half d_xb[TB*INS];         // x transposed to [t,b,k], fp16
__device__ __align__(128) __half d_wih0[G4*INS];
__device__ __align__(128) __half d_whh0[G4*HH];
__device__ __align__(128) __half d_wih1[G4*HH];
__device__ __align__(128) __half d_whh1[G4*HH];
__device__ __align__(128) float  d_gx[(size_t)TB*G4];  // 512MB, reused by both layers
__device__ __align__(128) __half d_h1[(size_t)TB*HH];  // layer0 outputs (row-major history)
__device__ __align__(128) __half d_h2[(size_t)TB*HH];  // layer1 outputs (row-major history)
// recurrent h in MMA fragment order, per group: [group2][ping2][4096 uint4]
__device__ __align__(128) __half d_hfrag[2*2*32*HH];
// one flag per CTA, padded to one 128B L2 line each; flag index = g*64+cg
__device__ __align__(128) unsigned d_flags[NCTA_REC * 32];
#define FLAG(i) d_flags[(i) << 5]

// ---------------------------------------------------------------------------
// Helpers
// ---------------------------------------------------------------------------
__device__ __forceinline__ void mma16816(float* d, const uint32_t* a, uint32_t b0, uint32_t b1) {
    asm volatile(
        "mma.sync.aligned.m16n8k16.row.col.f32.f16.f16.f32 "
        "{%0,%1,%2,%3},{%4,%5,%6,%7},{%8,%9},{%0,%1,%2,%3};\n"
        : "+f"(d[0]), "+f"(d[1]), "+f"(d[2]), "+f"(d[3])
        : "r"(a[0]), "r"(a[1]), "r"(a[2]), "r"(a[3]), "r"(b0), "r"(b1));
}

__device__ __forceinline__ void ldsm_x4(uint32_t& r0, uint32_t& r1, uint32_t& r2, uint32_t& r3,
                                        uint32_t addr) {
    asm volatile("ldmatrix.sync.aligned.m8n8.x4.shared.b16 {%0,%1,%2,%3}, [%4];"
                 : "=r"(r0), "=r"(r1), "=r"(r2), "=r"(r3) : "r"(addr));
}

__device__ __forceinline__ void cp16(uint32_t dst, const void* src) {
    asm volatile("cp.async.cg.shared.global [%0], [%1], 16;" :: "r"(dst), "l"(src));
}
#define CP_COMMIT()  asm volatile("cp.async.commit_group;")
#define CP_WAIT(n)   asm volatile("cp.async.wait_group %0;" :: "n"(n))

__device__ __forceinline__ unsigned ld_acq(const unsigned* p) {
    unsigned v;
    asm volatile("ld.global.acquire.gpu.b32 %0, [%1];" : "=r"(v) : "l"(p));
    return v;
}
__device__ __forceinline__ void st_rel(unsigned* p, unsigned v) {
    asm volatile("st.global.release.gpu.b32 [%0], %1;" :: "l"(p), "r"(v));
}

// L2-only 128b load (bypasses L1 -> no stale lines across ping-pong reuse)
__device__ __forceinline__ uint4 ldcg128(const uint4* p) {
    uint4 v;
    asm volatile("ld.global.cg.v4.u32 {%0,%1,%2,%3}, [%4];"
                 : "=r"(v.x), "=r"(v.y), "=r"(v.z), "=r"(v.w) : "l"(p));
    return v;
}

// Fast gate math (MUFU-based). Gate args bounded; ~1e-6 rel err << fp16 noise.
__device__ __forceinline__ float sigf(float x)   { return 1.0f / (1.0f + __expf(-x)); }
__device__ __forceinline__ float tanhfast(float x) {
    return 1.0f - 2.0f / (__expf(2.0f * x) + 1.0f);
}

// ---------------------------------------------------------------------------
// Conversions
// ---------------------------------------------------------------------------
__global__ void k_conv_x(const float* __restrict__ x, __half* __restrict__ xb) {
    int i = blockIdx.x * blockDim.x + threadIdx.x;   // over 2^24 elements
    int k = i & (INS - 1);
    int t = (i >> 9) & (TT - 1);
    int b = i >> 18;
    xb[(size_t)(t * BB + b) * INS + k] = __float2half(x[i]);
}

__global__ void k_conv_w(const float* __restrict__ s0, __half* __restrict__ o0, int n0,
                         const float* __restrict__ s1, __half* __restrict__ o1, int n1,
                         const float* __restrict__ s2, __half* __restrict__ o2, int n2,
                         const float* __restrict__ s3, __half* __restrict__ o3, int n3) {
    int i = blockIdx.x * blockDim.x + threadIdx.x;
    if (i < n0) o0[i] = __float2half(s0[i]);
    if (i < n1) o1[i] = __float2half(s1[i]);
    if (i < n2) o2[i] = __float2half(s2[i]);
    if (i < n3) o3[i] = __float2half(s3[i]);
}

// ---------------------------------------------------------------------------
// Batched GEMM (unchanged)
// ---------------------------------------------------------------------------
#define BM 128
#define BN 128
#define BK 64
#define KP 72   // padded k stride

__global__ __launch_bounds__(256) void k_gemm_bias(
    const __half* __restrict__ A,
    const __half* __restrict__ Bw,
    const float* __restrict__ bias1,
    const float* __restrict__ bias2,
    float* __restrict__ C, int M, int N, int K)
{
    extern __shared__ __half gsm_h[];
    __half* sAp = gsm_h;
    __half* sBp = gsm_h + 2 * BM * KP;

    const int bm = blockIdx.x * BM;
    const int bn = blockIdx.y * BN;
    const int tid  = threadIdx.x;
    const int w    = tid >> 5, lane = tid & 31;
    const int gid  = lane >> 2, lg = lane & 3;
    const int wm   = w >> 2, wn = w & 3;
    const int m0   = wm * 64, n0 = wn * 32;

    const int lrow = tid >> 3, lc = (tid & 7) * 8;

    const int lr8 = lane & 7, lsel = lane >> 3;
    const int a_row = lr8 + ((lsel & 1) << 3);
    const int a_col = (lsel >> 1) << 3;
    const int b_row = ((lsel >> 1) << 3) + lr8;
    const int b_col = (lsel & 1) << 3;

    uint32_t aBase0 = (uint32_t)__cvta_generic_to_shared(sAp);
    uint32_t bBase0 = (uint32_t)__cvta_generic_to_shared(sBp);
    const uint32_t bufA = (uint32_t)(BM * KP * 2);
    const uint32_t bufB = (uint32_t)(BN * KP * 2);

    float acc[4][4][4];
    #pragma unroll
    for (int mt = 0; mt < 4; mt++)
        #pragma unroll
        for (int nt = 0; nt < 4; nt++)
            #pragma unroll
            for (int r = 0; r < 4; r++) acc[mt][nt][r] = 0.0f;

    const int nc = K / BK;

    #pragma unroll
    for (int i = 0; i < 4; i++) {
        int row = lrow + i * 32;
        cp16(aBase0 + (uint32_t)((row * KP + lc) * 2), &A[(size_t)(bm + row) * K + lc]);
        cp16(bBase0 + (uint32_t)((row * KP + lc) * 2), &Bw[(size_t)(bn + row) * K + lc]);
    }
    CP_COMMIT();

    for (int c = 0; c < nc; c++) {
        if (c + 1 < nc) {
            int kc = (c + 1) * BK;
            uint32_t dA = aBase0 + ((c + 1) & 1) * bufA;
            uint32_t dB = bBase0 + ((c + 1) & 1) * bufB;
            #pragma unroll
            for (int i = 0; i < 4; i++) {
                int row = lrow + i * 32;
                cp16(dA + (uint32_t)((row * KP + lc) * 2), &A[(size_t)(bm + row) * K + kc + lc]);
                cp16(dB + (uint32_t)((row * KP + lc) * 2), &Bw[(size_t)(bn + row) * K + kc + lc]);
            }
            CP_COMMIT();
            CP_WAIT(1);
        } else {
            CP_WAIT(0);
        }
        __syncthreads();

        uint32_t aB = aBase0 + (c & 1) * bufA;
        uint32_t bB = bBase0 + (c & 1) * bufB;

        #pragma unroll
        for (int ks = 0; ks < BK / 16; ks++) {
            const int kb = ks * 16;
            uint32_t a[4][4];
            #pragma unroll
            for (int mt = 0; mt < 4; mt++) {
                uint32_t addr = aB + (uint32_t)(((m0 + mt * 16 + a_row) * KP + kb + a_col) * 2);
                ldsm_x4(a[mt][0], a[mt][1], a[mt][2], a[mt][3], addr);
            }
            uint32_t b[4][2];
            #pragma unroll
            for (int np = 0; np < 2; np++) {
                uint32_t addr = bB + (uint32_t)(((n0 + np * 16 + b_row) * KP + kb + b_col) * 2);
                uint32_t r0, r1, r2, r3;
                ldsm_x4(r0, r1, r2, r3, addr);
                b[np * 2][0] = r0;     b[np * 2][1] = r1;
                b[np * 2 + 1][0] = r2; b[np * 2 + 1][1] = r3;
            }
            #pragma unroll
            for (int nt = 0; nt < 4; nt++)
                #pragma unroll
                for (int mt = 0; mt < 4; mt++)
                    mma16816(acc[mt][nt], a[mt], b[nt][0], b[nt][1]);
        }
        __syncthreads();
    }

    #pragma unroll
    for (int mt = 0; mt < 4; mt++) {
        #pragma unroll
        for (int nt = 0; nt < 4; nt++) {
            int gm1 = bm + m0 + mt * 16 + gid;
            int gn  = bn + n0 + nt * 8 + lg * 2;
            float bi0 = bias1[gn] + bias2[gn];
            float bi1 = bias1[gn + 1] + bias2[gn + 1];
            float2 v0 = make_float2(acc[mt][nt][0] + bi0, acc[mt][nt][1] + bi1);
            float2 v1 = make_float2(acc[mt][nt][2] + bi0, acc[mt][nt][3] + bi1);
            *reinterpret_cast<float2*>(&C[(size_t)gm1 * N + gn]) = v0;
            *reinterpret_cast<float2*>(&C[(size_t)(gm1 + 8) * N + gn]) = v1;
        }
    }
}

// ---------------------------------------------------------------------------
// Persistent LSTM recurrence — batch-split + PRECISE per-warp producer wait.
// (R13 structure; sync-1 removed.)
// 2 independent groups of 64 CTAs; group g handles batch rows [g*32,+32);
// CTA cg owns 16 units (64 gate rows), w_hh slice resident in smem.
// 16 warps = (kq4 x ng2) K-segments x mt2 M-tiles; per warp M=16, N=64,
// K=128. A-fragments of segment seg are produced by EXACTLY the 8 CTAs
// cg = seg*8 + ks -> lanes 0-7 of each warp poll those 8 padded flag lines
// and the warp proceeds immediately (no CTA-wide sync; 2 pollers/CTA/flag =
// 128 chip-wide, same proven density as R11). WAR on the fragment slot is
// safe: the pointwise overwrite happens after sync "partials", which all 16
// warps reach only after their polls (union = all 64 group flags >= t).
// Tail: 8 K-segment partials -> ONE sync -> 512-wide pointwise -> sync ->
// release publish. 2 CTA syncs/step.
// ---------------------------------------------------------------------------
__global__ __launch_bounds__(REC_THREADS) void k_lstm_rec(
    const float* __restrict__ gx,           // [T*B, 4096]
    const __half* __restrict__ whh,         // [4096, 1024] fp16
    __half* __restrict__ hall)              // [T*B, H] fp16 (row-major history)
{
    extern __shared__ __align__(16) char smem[];
    __half* wsm = reinterpret_cast<__half*>(smem);          // 64 * HS (w_hh slice)
    float* pbuf = reinterpret_cast<float*>(wsm + 64 * HS);  // 8 * PB partials

    const int tid = threadIdx.x;
    const int cta = blockIdx.x;
    const int g   = cta >> 6;          // batch group
    const int cg  = cta & 63;          // CTA within group
    const int j0  = cg * 16;           // first owned unit
    const int lane = tid & 31, w = tid >> 5;
    const int gid = lane >> 2, lg = lane & 3;
    const int kq = w >> 2;             // K quarter 0..3
    const int mt = (w >> 1) & 1;       // M tile 0..1 (M=32)
    const int ng = w & 1;              // K-eighth within quarter
    const int seg = kq * 2 + ng;       // K segment 0..7 (128 cols each)
    const int m0 = mt * 16;

    const uint32_t wsm_u = (uint32_t)__cvta_generic_to_shared(wsm);

    // LDSM lane addressing (B operand): 4 x4-loads cover 64 rows x 16 cols
    const int lr8 = lane & 7, lsel = lane >> 3;
    const int b_row = ((lsel >> 1) << 3) + lr8;
    const int b_col = (lsel & 1) << 3;
    uint32_t bAddr[4];
    #pragma unroll
    for (int p = 0; p < 4; p++)
        bAddr[p] = wsm_u + (uint32_t)(((p * 16 + b_row) * HS + seg * 128 + b_col) * 2);

    // A-fragment source: group-local buffer of 4096 uint4; warp block wA
    const int wA = seg * 2 + mt;
    const int hfw_off = (wA * 8) * 32 + lane;      // + ks*32 per iteration
    const uint4* fragbase = reinterpret_cast<const uint4*>(d_hfrag);

    // Load this CTA's 64 gate rows of w_hh into smem (once).
    #pragma unroll
    for (int i = 0; i < 16; i++) {
        int idx = tid + i * REC_THREADS;    // 0..8191
        int row = idx >> 7, c8 = idx & 127;
        int grow = (row >> 4) * HH + j0 + (row & 15);
        *reinterpret_cast<uint4*>(&wsm[row * HS + c8 * 8]) =
            *reinterpret_cast<const uint4*>(&whh[(size_t)grow * HH + c8 * 8]);
    }

    // pointwise ownership: thread -> (b_local = tid>>4, jj = tid&15)
    const int pw_b = tid >> 4, pw_j = tid & 15;
    float creg = 0.0f;
    // producer fragment offset (within group-ping buffer); CTA-fixed seg/ks
    size_t fragoff;
    {
        int mtp = pw_b >> 4, gidp = pw_b & 7, rhalf = (pw_b >> 3) & 1;
        int segp = cg >> 3, ksp = cg & 7;
        int khalf = pw_j >> 3, lgp = (pw_j & 7) >> 1, odd = pw_j & 1;
        int wAp = segp * 2 + mtp;
        int lanep = gidp * 4 + lgp;
        int regp = rhalf + 2 * khalf;
        fragoff = ((size_t)((wAp * 8 + ksp) * 32 + lanep)) * 8 + regp * 2 + odd;
    }

    // PRECISE polling: lanes 0-7 poll the 8 producer CTAs of this warp's
    // segment (cg = seg*8 + ks). 2 pollers per CTA per flag line.
    const int fidx = g * 64 + seg * 8 + (lane & 7);
    unsigned basef = 0;
    if (lane < 8) basef = ld_acq(&FLAG(fidx));
    unsigned base0;
    {
        __shared__ unsigned sb;
        if (tid == 0) sb = ld_acq(&FLAG(g * 64 + cg));
        __syncthreads();
        base0 = sb;
    }

    for (int t = 0; t < TT; t++) {
        // gx prefetch: this thread's 4 gate inputs (independent of h(t))
        float gxv[4];
        {
            const float* gp = gx + ((size_t)(t * BB) + g * 32 + pw_b) * G4 + j0 + pw_j;
            #pragma unroll
            for (int gt = 0; gt < 4; gt++) gxv[gt] = gp[gt * HH];
        }

        float acc[8][4];
        #pragma unroll
        for (int nt = 0; nt < 8; nt++)
            #pragma unroll
            for (int r = 0; r < 4; r++) acc[nt][r] = 0.0f;

        if (t > 0) {
            // per-warp precise wait on this segment's 8 producers, then go
            if (lane < 8) {
                unsigned target = basef + (unsigned)t;
                while ((int)(ld_acq(&FLAG(fidx)) - target) < 0) __nanosleep(32);
            }
            __syncwarp();

            const uint4* hfw = fragbase + ((size_t)(g * 2 + (t & 1))) * 4096 + hfw_off;

            // A-fragments from L2, 2 groups of 4, double-buffered vs MMA
            uint4 af[2][4];
            #pragma unroll
            for (int q = 0; q < 4; q++) af[0][q] = ldcg128(hfw + q * 32);

            #pragma unroll
            for (int gb = 0; gb < 2; gb++) {
                if (gb == 0) {
                    #pragma unroll
                    for (int q = 0; q < 4; q++)
                        af[1][q] = ldcg128(hfw + (4 + q) * 32);
                }
                #pragma unroll
                for (int q = 0; q < 4; q++) {
                    const int ks = gb * 4 + q;
                    const uint32_t koff = (uint32_t)(ks * 32);
                    const uint32_t* a = reinterpret_cast<const uint32_t*>(&af[gb][q]);
                    #pragma unroll
                    for (int p = 0; p < 4; p++) {
                        uint32_t b0, b1, b2, b3;
                        ldsm_x4(b0, b1, b2, b3, bAddr[p] + koff);
                        mma16816(acc[p * 2], a, b0, b1);
                        mma16816(acc[p * 2 + 1], a, b2, b3);
                    }
                }
            }
        }
        // t == 0: h == 0 -> acc stays 0.

        // write this warp's partials to its K-segment buffer
        {
            float* pb = pbuf + seg * PB;
            const int r0o = (m0 + gid) * 65, r1o = (m0 + gid + 8) * 65;
            #pragma unroll
            for (int nt = 0; nt < 8; nt++) {
                int col = nt * 8 + lg * 2;
                pb[r0o + col]     = acc[nt][0];  pb[r0o + col + 1] = acc[nt][1];
                pb[r1o + col]     = acc[nt][2];  pb[r1o + col + 1] = acc[nt][3];
            }
        }
        __syncthreads();   // sync A: partials visible (and all polls passed)

        // pointwise: sum 8 K-segment partials + gx for this (b_local, jj)
        unsigned short hb;
        {
            const int o = pw_b * 65 + pw_j;
            float v[4];
            #pragma unroll
            for (int gt = 0; gt < 4; gt++) {
                const int oo = o + gt * 16;
                float s = gxv[gt];
                #pragma unroll
                for (int sgi = 0; sgi < 8; sgi++) s += pbuf[sgi * PB + oo];
                v[gt] = s;
            }
            creg = sigf(v[1]) * creg + sigf(v[0]) * tanhfast(v[2]);
            float h = sigf(v[3]) * tanhfast(creg);
            hb = __half_as_ushort(__float2half(h));
            *reinterpret_cast<unsigned short*>(
                &d_hfrag[((size_t)(g * 2 + ((t + 1) & 1))) * (32 * HH) + fragoff]) = hb;
        }
        __syncthreads();   // sync B: hfrag stores done CTA-wide

        if (tid == 0) {
            st_rel(&FLAG(g * 64 + cg), base0 + (unsigned)t + 1u);
        }

        // row-major history store off the critical path (later kernels only)
        *reinterpret_cast<unsigned short*>(
            &hall[((size_t)(t * BB) + g * 32 + pw_b) * HH + j0 + pw_j]) = hb;
    }
}

// ---------------------------------------------------------------------------
// Output projection (unchanged)
// ---------------------------------------------------------------------------
__global__ void k_out(const __half* __restrict__ h2,
                      const float* __restrict__ wout,
                      const float* __restrict__ bout,
                      float* __restrict__ out)
{
    int wg = (blockIdx.x * blockDim.x + threadIdx.x) >> 5;
    int lane = threadIdx.x & 31;
    if (wg >= TB) return;
    int t = wg >> 6;     // / BB
    int b = wg & 63;
    const __half* hp = h2 + (size_t)wg * HH;
    float sum = 0.0f;
    #pragma unroll
    for (int i = 0; i < 4; i++) {
        int k = i * 256 + lane * 8;
        uint4 v = *reinterpret_cast<const uint4*>(&hp[k]);
        const __half* pv = reinterpret_cast<const __half*>(&v);
        float4 w0 = *reinterpret_cast<const float4*>(&wout[k]);
        float4 w1 = *reinterpret_cast<const float4*>(&wout[k + 4]);
        sum += __half2float(pv[0]) * w0.x + __half2float(pv[1]) * w0.y
             + __half2float(pv[2]) * w0.z + __half2float(pv[3]) * w0.w
             + __half2float(pv[4]) * w1.x + __half2float(pv[5]) * w1.y
             + __half2float(pv[6]) * w1.z + __half2float(pv[7]) * w1.w;
    }
    #pragma unroll
    for (int off = 16; off; off >>= 1) sum += __shfl_xor_sync(0xffffffffu, sum, off);
    if (lane == 0) out[(size_t)b * TT + t] = sum + bout[0];
}

// ---------------------------------------------------------------------------
// Launch. Stream order keeps k_lstm_rec (layer 0) at our launch index 3 (the
// ncu capture slot).
// ---------------------------------------------------------------------------
extern "C" void kernel_launch(void* const* d_in, const int* in_sizes, int n_in,
                              void* d_out, int out_size)
{
    const float* x     = (const float*)d_in[0];
    const float* w_ih0 = (const float*)d_in[1];
    const float* w_hh0 = (const float*)d_in[2];
    const float* b_ih0 = (const float*)d_in[3];
    const float* b_hh0 = (const float*)d_in[4];
    const float* w_ih1 = (const float*)d_in[5];
    const float* w_hh1 = (const float*)d_in[6];
    const float* b_ih1 = (const float*)d_in[7];
    const float* b_hh1 = (const float*)d_in[8];
    const float* w_out = (const float*)d_in[9];
    const float* b_out = (const float*)d_in[10];
    float* out = (float*)d_out;

    void *p_xb, *p_wih0, *p_whh0, *p_wih1, *p_whh1, *p_gx, *p_h1, *p_h2;
    cudaGetSymbolAddress(&p_xb, d_xb);
    cudaGetSymbolAddress(&p_wih0, d_wih0);
    cudaGetSymbolAddress(&p_whh0, d_whh0);
    cudaGetSymbolAddress(&p_wih1, d_wih1);
    cudaGetSymbolAddress(&p_whh1, d_whh1);
    cudaGetSymbolAddress(&p_gx, d_gx);
    cudaGetSymbolAddress(&p_h1, d_h1);
    cudaGetSymbolAddress(&p_h2, d_h2);

    const int SMEM_REC  = 64 * HS * 2 + 8 * PB * 4;               // 198656 B
    const int SMEM_GEMM = (2 * BM * KP + 2 * BN * KP) * 2;        // 73728 B
    cudaFuncSetAttribute(k_lstm_rec, cudaFuncAttributeMaxDynamicSharedMemorySize, SMEM_REC);
    cudaFuncSetAttribute(k_gemm_bias, cudaFuncAttributeMaxDynamicSharedMemorySize, SMEM_GEMM);

    // idx 0: x conversion
    k_conv_x<<<(TB * INS) / 256, 256>>>(x, (__half*)p_xb);
    // idx 1: all weight conversions fused
    k_conv_w<<<(G4 * HH) / 256, 256>>>(w_ih0, (__half*)p_wih0, G4 * INS,
                                       w_hh0, (__half*)p_whh0, G4 * HH,
                                       w_ih1, (__half*)p_wih1, G4 * HH,
                                       w_hh1, (__half*)p_whh1, G4 * HH);

    dim3 gg(TB / BM, G4 / BN);

    // idx 2: gx0 = x @ w_ih0^T + biases
    k_gemm_bias<<<gg, 256, SMEM_GEMM>>>((__half*)p_xb, (__half*)p_wih0,
                                        b_ih0, b_hh0, (float*)p_gx, TB, G4, INS);
    // idx 3: layer-0 recurrence  (ncu capture target)
    k_lstm_rec<<<NCTA_REC, REC_THREADS, SMEM_REC>>>((float*)p_gx, (__half*)p_whh0,
                                                    (__half*)p_h1);

    // idx 4: gx1 = h1 @ w_ih1^T + biases ; idx 5: layer-1 recurrence
    k_gemm_bias<<<gg, 256, SMEM_GEMM>>>((__half*)p_h1, (__half*)p_wih1,
                                        b_ih1, b_hh1, (float*)p_gx, TB, G4, HH);
    k_lstm_rec<<<NCTA_REC, REC_THREADS, SMEM_REC>>>((float*)p_gx, (__half*)p_whh1,
                                                    (__half*)p_h2);

    // idx 6: output projection
    k_out<<<(TB * 32) / 256, 256>>>((__half*)p_h2, w_out, b_out, out);
}

// round 17
// speedup vs baseline: 1.2041x; 1.1248x over previous
#include <cuda_runtime.h>
#include <cuda_fp16.h>
#include <math.h>
#include <stdint.h>

// Problem dims
#define BB   64
#define TT   512
#define INS  512
#define HH   1024
#define G4   4096          // 4*HH
#define TB   (TT*BB)       // 32768

// Recurrence kernel config: 2 independent batch groups x 64 CTAs.
// CTA owns 16 units (64 gate rows, gate-interleaved) for its group's 32 rows.
#define NCTA_REC 128
#define HS       (HH+8)    // padded smem row stride (fp16) for the w_hh tile
#define REC_THREADS 512    // 16 warps: (kq4 x ng2) k-segments x mt2
#define PB       (32*68)   // partial buffer: 32 batch rows x 64 cols (pad 68 -> 16B-aligned rows)

// ---------------------------------------------------------------------------
// Scratch (device globals; no allocation allowed)
// ---------------------------------------------------------------------------
__device__ __align__(128) __half d_xb[TB*INS];         // x transposed to [t,b,k], fp16
__device__ __align__(128) __half d_wih0[G4*INS];
__device__ __align__(128) __half d_whh0[G4*HH];
__device__ __align__(128) __half d_wih1[G4*HH];
__device__ __align__(128) __half d_whh1[G4*HH];
__device__ __align__(128) float  d_gx[(size_t)TB*G4];  // gx in [t, b, unit, gate] interleave
__device__ __align__(128) __half d_h1[(size_t)TB*HH];  // layer0 outputs (row-major history)
__device__ __align__(128) __half d_h2[(size_t)TB*HH];  // layer1 outputs (row-major history)
// recurrent h in MMA fragment order, per group: [group2][ping2][4096 uint4]
__device__ __align__(128) __half d_hfrag[2*2*32*HH];
// one flag per CTA, padded to one 128B L2 line each; flag index = g*64+cg
__device__ __align__(128) unsigned d_flags[NCTA_REC * 32];
#define FLAG(i) d_flags[(i) << 5]

// ---------------------------------------------------------------------------
// Helpers
// ---------------------------------------------------------------------------
__device__ __forceinline__ void mma16816(float* d, const uint32_t* a, uint32_t b0, uint32_t b1) {
    asm volatile(
        "mma.sync.aligned.m16n8k16.row.col.f32.f16.f16.f32 "
        "{%0,%1,%2,%3},{%4,%5,%6,%7},{%8,%9},{%0,%1,%2,%3};\n"
        : "+f"(d[0]), "+f"(d[1]), "+f"(d[2]), "+f"(d[3])
        : "r"(a[0]), "r"(a[1]), "r"(a[2]), "r"(a[3]), "r"(b0), "r"(b1));
}

__device__ __forceinline__ void ldsm_x4(uint32_t& r0, uint32_t& r1, uint32_t& r2, uint32_t& r3,
                                        uint32_t addr) {
    asm volatile("ldmatrix.sync.aligned.m8n8.x4.shared.b16 {%0,%1,%2,%3}, [%4];"
                 : "=r"(r0), "=r"(r1), "=r"(r2), "=r"(r3) : "r"(addr));
}

__device__ __forceinline__ void cp16(uint32_t dst, const void* src) {
    asm volatile("cp.async.cg.shared.global [%0], [%1], 16;" :: "r"(dst), "l"(src));
}
#define CP_COMMIT()  asm volatile("cp.async.commit_group;")
#define CP_WAIT(n)   asm volatile("cp.async.wait_group %0;" :: "n"(n))

__device__ __forceinline__ unsigned ld_acq(const unsigned* p) {
    unsigned v;
    asm volatile("ld.global.acquire.gpu.b32 %0, [%1];" : "=r"(v) : "l"(p));
    return v;
}
__device__ __forceinline__ void st_rel(unsigned* p, unsigned v) {
    asm volatile("st.global.release.gpu.b32 [%0], %1;" :: "l"(p), "r"(v));
}

// L2-only 128b load (bypasses L1 -> no stale lines across ping-pong reuse)
__device__ __forceinline__ uint4 ldcg128(const uint4* p) {
    uint4 v;
    asm volatile("ld.global.cg.v4.u32 {%0,%1,%2,%3}, [%4];"
                 : "=r"(v.x), "=r"(v.y), "=r"(v.z), "=r"(v.w) : "l"(p));
    return v;
}

// Fast gate math (MUFU-based). Gate args bounded; ~1e-6 rel err << fp16 noise.
__device__ __forceinline__ float sigf(float x)   { return 1.0f / (1.0f + __expf(-x)); }
__device__ __forceinline__ float tanhfast(float x) {
    return 1.0f - 2.0f / (__expf(2.0f * x) + 1.0f);
}

// ---------------------------------------------------------------------------
// Conversions
// ---------------------------------------------------------------------------
__global__ void k_conv_x(const float* __restrict__ x, __half* __restrict__ xb) {
    int i = blockIdx.x * blockDim.x + threadIdx.x;   // over 2^24 elements
    int k = i & (INS - 1);
    int t = (i >> 9) & (TT - 1);
    int b = i >> 18;
    xb[(size_t)(t * BB + b) * INS + k] = __float2half(x[i]);
}

__global__ void k_conv_w(const float* __restrict__ s0, __half* __restrict__ o0, int n0,
                         const float* __restrict__ s1, __half* __restrict__ o1, int n1,
                         const float* __restrict__ s2, __half* __restrict__ o2, int n2,
                         const float* __restrict__ s3, __half* __restrict__ o3, int n3) {
    int i = blockIdx.x * blockDim.x + threadIdx.x;
    if (i < n0) o0[i] = __float2half(s0[i]);
    if (i < n1) o1[i] = __float2half(s1[i]);
    if (i < n2) o2[i] = __float2half(s2[i]);
    if (i < n3) o3[i] = __float2half(s3[i]);
}

// ---------------------------------------------------------------------------
// Batched GEMM: C[M, 4096] fp32 in GATE-INTERLEAVED column order
// (col c = unit*4 + gate). B rows gathered: tile row r -> w_ih row
// (r&3)*HH + u0 + (r>>2). Stores stay fully coalesced. Bias remapped.
// ---------------------------------------------------------------------------
#define BM 128
#define BN 128
#define BK 64
#define KP 72   // padded k stride

__global__ __launch_bounds__(256) void k_gemm_bias(
    const __half* __restrict__ A,
    const __half* __restrict__ Bw,
    const float* __restrict__ bias1,
    const float* __restrict__ bias2,
    float* __restrict__ C, int M, int N, int K)
{
    extern __shared__ __half gsm_h[];
    __half* sAp = gsm_h;
    __half* sBp = gsm_h + 2 * BM * KP;

    const int bm = blockIdx.x * BM;
    const int bn = blockIdx.y * BN;
    const int u0 = bn >> 2;            // first unit of this column block
    const int tid  = threadIdx.x;
    const int w    = tid >> 5, lane = tid & 31;
    const int gid  = lane >> 2, lg = lane & 3;
    const int wm   = w >> 2, wn = w & 3;
    const int m0   = wm * 64, n0 = wn * 32;

    const int lrow = tid >> 3, lc = (tid & 7) * 8;

    const int lr8 = lane & 7, lsel = lane >> 3;
    const int a_row = lr8 + ((lsel & 1) << 3);
    const int a_col = (lsel >> 1) << 3;
    const int b_row = ((lsel >> 1) << 3) + lr8;
    const int b_col = (lsel & 1) << 3;

    uint32_t aBase0 = (uint32_t)__cvta_generic_to_shared(sAp);
    uint32_t bBase0 = (uint32_t)__cvta_generic_to_shared(sBp);
    const uint32_t bufA = (uint32_t)(BM * KP * 2);
    const uint32_t bufB = (uint32_t)(BN * KP * 2);

    float acc[4][4][4];
    #pragma unroll
    for (int mt = 0; mt < 4; mt++)
        #pragma unroll
        for (int nt = 0; nt < 4; nt++)
            #pragma unroll
            for (int r = 0; r < 4; r++) acc[mt][nt][r] = 0.0f;

    const int nc = K / BK;

    #pragma unroll
    for (int i = 0; i < 4; i++) {
        int row = lrow + i * 32;
        int brow = (row & 3) * HH + u0 + (row >> 2);   // gate-interleave gather
        cp16(aBase0 + (uint32_t)((row * KP + lc) * 2), &A[(size_t)(bm + row) * K + lc]);
        cp16(bBase0 + (uint32_t)((row * KP + lc) * 2), &Bw[(size_t)brow * K + lc]);
    }
    CP_COMMIT();

    for (int c = 0; c < nc; c++) {
        if (c + 1 < nc) {
            int kc = (c + 1) * BK;
            uint32_t dA = aBase0 + ((c + 1) & 1) * bufA;
            uint32_t dB = bBase0 + ((c + 1) & 1) * bufB;
            #pragma unroll
            for (int i = 0; i < 4; i++) {
                int row = lrow + i * 32;
                int brow = (row & 3) * HH + u0 + (row >> 2);
                cp16(dA + (uint32_t)((row * KP + lc) * 2), &A[(size_t)(bm + row) * K + kc + lc]);
                cp16(dB + (uint32_t)((row * KP + lc) * 2), &Bw[(size_t)brow * K + kc + lc]);
            }
            CP_COMMIT();
            CP_WAIT(1);
        } else {
            CP_WAIT(0);
        }
        __syncthreads();

        uint32_t aB = aBase0 + (c & 1) * bufA;
        uint32_t bB = bBase0 + (c & 1) * bufB;

        #pragma unroll
        for (int ks = 0; ks < BK / 16; ks++) {
            const int kb = ks * 16;
            uint32_t a[4][4];
            #pragma unroll
            for (int mt = 0; mt < 4; mt++) {
                uint32_t addr = aB + (uint32_t)(((m0 + mt * 16 + a_row) * KP + kb + a_col) * 2);
                ldsm_x4(a[mt][0], a[mt][1], a[mt][2], a[mt][3], addr);
            }
            uint32_t b[4][2];
            #pragma unroll
            for (int np = 0; np < 2; np++) {
                uint32_t addr = bB + (uint32_t)(((n0 + np * 16 + b_row) * KP + kb + b_col) * 2);
                uint32_t r0, r1, r2, r3;
                ldsm_x4(r0, r1, r2, r3, addr);
                b[np * 2][0] = r0;     b[np * 2][1] = r1;
                b[np * 2 + 1][0] = r2; b[np * 2 + 1][1] = r3;
            }
            #pragma unroll
            for (int nt = 0; nt < 4; nt++)
                #pragma unroll
                for (int mt = 0; mt < 4; mt++)
                    mma16816(acc[mt][nt], a[mt], b[nt][0], b[nt][1]);
        }
        __syncthreads();
    }

    #pragma unroll
    for (int mt = 0; mt < 4; mt++) {
        #pragma unroll
        for (int nt = 0; nt < 4; nt++) {
            int gm1 = bm + m0 + mt * 16 + gid;
            int gn  = bn + n0 + nt * 8 + lg * 2;        // interleaved col index
            int bi_idx0 = (gn & 3) * HH + (gn >> 2);
            int bi_idx1 = ((gn + 1) & 3) * HH + ((gn + 1) >> 2);
            float bi0 = bias1[bi_idx0] + bias2[bi_idx0];
            float bi1 = bias1[bi_idx1] + bias2[bi_idx1];
            float2 v0 = make_float2(acc[mt][nt][0] + bi0, acc[mt][nt][1] + bi1);
            float2 v1 = make_float2(acc[mt][nt][2] + bi0, acc[mt][nt][3] + bi1);
            *reinterpret_cast<float2*>(&C[(size_t)gm1 * N + gn]) = v0;
            *reinterpret_cast<float2*>(&C[(size_t)(gm1 + 8) * N + gn]) = v1;
        }
    }
}

// ---------------------------------------------------------------------------
// Persistent LSTM recurrence — batch-split + precise per-warp producer wait
// + gate-interleaved gx/partials.
// 2 independent groups of 64 CTAs; group g handles batch rows [g*32,+32);
// CTA cg owns 16 units; w_hh slice resident in smem with B-tile rows in
// (unit_local, gate) interleave -> partial cols = unit_local*4 + gate ->
// pointwise reads ONE float4 per segment + ONE float4 of gx.
// A-fragments of segment seg are produced by exactly the 8 CTAs cg=seg*8+ks;
// lanes 0-7 of each warp poll those flags and the warp proceeds (2 CTA
// syncs/step total).
// ---------------------------------------------------------------------------
__global__ __launch_bounds__(REC_THREADS) void k_lstm_rec(
    const float* __restrict__ gx,           // [T*B, 4096] gate-interleaved
    const __half* __restrict__ whh,         // [4096, 1024] fp16
    __half* __restrict__ hall)              // [T*B, H] fp16 (row-major history)
{
    extern __shared__ __align__(16) char smem[];
    __half* wsm = reinterpret_cast<__half*>(smem);          // 64 * HS (w_hh slice)
    float* pbuf = reinterpret_cast<float*>(wsm + 64 * HS);  // 8 * PB partials

    const int tid = threadIdx.x;
    const int cta = blockIdx.x;
    const int g   = cta >> 6;          // batch group
    const int cg  = cta & 63;          // CTA within group
    const int j0  = cg * 16;           // first owned unit
    const int lane = tid & 31, w = tid >> 5;
    const int gid = lane >> 2, lg = lane & 3;
    const int kq = w >> 2;             // K quarter 0..3
    const int mt = (w >> 1) & 1;       // M tile 0..1 (M=32)
    const int ng = w & 1;              // K-eighth within quarter
    const int seg = kq * 2 + ng;       // K segment 0..7 (128 cols each)
    const int m0 = mt * 16;

    const uint32_t wsm_u = (uint32_t)__cvta_generic_to_shared(wsm);

    // LDSM lane addressing (B operand): 4 x4-loads cover 64 rows x 16 cols
    const int lr8 = lane & 7, lsel = lane >> 3;
    const int b_row = ((lsel >> 1) << 3) + lr8;
    const int b_col = (lsel & 1) << 3;
    uint32_t bAddr[4];
    #pragma unroll
    for (int p = 0; p < 4; p++)
        bAddr[p] = wsm_u + (uint32_t)(((p * 16 + b_row) * HS + seg * 128 + b_col) * 2);

    // A-fragment source: group-local buffer of 4096 uint4; warp block wA
    const int wA = seg * 2 + mt;
    const int hfw_off = (wA * 8) * 32 + lane;      // + ks*32 per iteration
    const uint4* fragbase = reinterpret_cast<const uint4*>(d_hfrag);

    // Load this CTA's 64 gate rows of w_hh into smem (once), interleaved:
    // smem B-tile row r -> unit_local r>>2, gate r&3 -> w_hh row (r&3)*HH + j0 + (r>>2)
    #pragma unroll
    for (int i = 0; i < 16; i++) {
        int idx = tid + i * REC_THREADS;    // 0..8191
        int row = idx >> 7, c8 = idx & 127;
        int grow = (row & 3) * HH + j0 + (row >> 2);
        *reinterpret_cast<uint4*>(&wsm[row * HS + c8 * 8]) =
            *reinterpret_cast<const uint4*>(&whh[(size_t)grow * HH + c8 * 8]);
    }

    // pointwise ownership: thread -> (b_local = tid>>4, jj = tid&15)
    const int pw_b = tid >> 4, pw_j = tid & 15;
    float creg = 0.0f;
    // producer fragment offset (within group-ping buffer); CTA-fixed seg/ks
    size_t fragoff;
    {
        int mtp = pw_b >> 4, gidp = pw_b & 7, rhalf = (pw_b >> 3) & 1;
        int segp = cg >> 3, ksp = cg & 7;
        int khalf = pw_j >> 3, lgp = (pw_j & 7) >> 1, odd = pw_j & 1;
        int wAp = segp * 2 + mtp;
        int lanep = gidp * 4 + lgp;
        int regp = rhalf + 2 * khalf;
        fragoff = ((size_t)((wAp * 8 + ksp) * 32 + lanep)) * 8 + regp * 2 + odd;
    }

    // PRECISE polling: lanes 0-7 poll the 8 producer CTAs of this warp's
    // segment (cg = seg*8 + ks). 2 pollers per CTA per flag line.
    const int fidx = g * 64 + seg * 8 + (lane & 7);
    unsigned basef = 0;
    if (lane < 8) basef = ld_acq(&FLAG(fidx));
    unsigned base0;
    {
        __shared__ unsigned sb;
        if (tid == 0) sb = ld_acq(&FLAG(g * 64 + cg));
        __syncthreads();
        base0 = sb;
    }

    for (int t = 0; t < TT; t++) {
        // gx prefetch: ONE coalesced 16B load = 4 gates of (b, unit)
        float gxv[4];
        {
            const uint4 gv = ldcg128(reinterpret_cast<const uint4*>(
                gx + ((size_t)(t * BB) + g * 32 + pw_b) * G4 + (size_t)(j0 + pw_j) * 4));
            gxv[0] = __uint_as_float(gv.x);
            gxv[1] = __uint_as_float(gv.y);
            gxv[2] = __uint_as_float(gv.z);
            gxv[3] = __uint_as_float(gv.w);
        }

        float acc[8][4];
        #pragma unroll
        for (int nt = 0; nt < 8; nt++)
            #pragma unroll
            for (int r = 0; r < 4; r++) acc[nt][r] = 0.0f;

        if (t > 0) {
            // per-warp precise wait on this segment's 8 producers, then go
            if (lane < 8) {
                unsigned target = basef + (unsigned)t;
                while ((int)(ld_acq(&FLAG(fidx)) - target) < 0) __nanosleep(32);
            }
            __syncwarp();

            const uint4* hfw = fragbase + ((size_t)(g * 2 + (t & 1))) * 4096 + hfw_off;

            // A-fragments from L2, 2 groups of 4, double-buffered vs MMA
            uint4 af[2][4];
            #pragma unroll
            for (int q = 0; q < 4; q++) af[0][q] = ldcg128(hfw + q * 32);

            #pragma unroll
            for (int gb = 0; gb < 2; gb++) {
                if (gb == 0) {
                    #pragma unroll
                    for (int q = 0; q < 4; q++)
                        af[1][q] = ldcg128(hfw + (4 + q) * 32);
                }
                #pragma unroll
                for (int q = 0; q < 4; q++) {
                    const int ks = gb * 4 + q;
                    const uint32_t koff = (uint32_t)(ks * 32);
                    const uint32_t* a = reinterpret_cast<const uint32_t*>(&af[gb][q]);
                    #pragma unroll
                    for (int p = 0; p < 4; p++) {
                        uint32_t b0, b1, b2, b3;
                        ldsm_x4(b0, b1, b2, b3, bAddr[p] + koff);
                        mma16816(acc[p * 2], a, b0, b1);
                        mma16816(acc[p * 2 + 1], a, b2, b3);
                    }
                }
            }
        }
        // t == 0: h == 0 -> acc stays 0.

        // write this warp's partials to its K-segment buffer (interleaved cols)
        {
            float* pb = pbuf + seg * PB;
            const int r0o = (m0 + gid) * 68, r1o = (m0 + gid + 8) * 68;
            #pragma unroll
            for (int nt = 0; nt < 8; nt++) {
                int col = nt * 8 + lg * 2;
                pb[r0o + col]     = acc[nt][0];  pb[r0o + col + 1] = acc[nt][1];
                pb[r1o + col]     = acc[nt][2];  pb[r1o + col + 1] = acc[nt][3];
            }
        }
        __syncthreads();   // sync A: partials visible (and all polls passed)

        // pointwise: gx float4 + 8 partial float4s (gates contiguous)
        unsigned short hb;
        {
            const int o = pw_b * 68 + pw_j * 4;
            float si = gxv[0], sf = gxv[1], sg = gxv[2], so = gxv[3];
            #pragma unroll
            for (int sgi = 0; sgi < 8; sgi++) {
                const float4 p4 = *reinterpret_cast<const float4*>(&pbuf[sgi * PB + o]);
                si += p4.x; sf += p4.y; sg += p4.z; so += p4.w;
            }
            creg = sigf(sf) * creg + sigf(si) * tanhfast(sg);
            float h = sigf(so) * tanhfast(creg);
            hb = __half_as_ushort(__float2half(h));
            *reinterpret_cast<unsigned short*>(
                &d_hfrag[((size_t)(g * 2 + ((t + 1) & 1))) * (32 * HH) + fragoff]) = hb;
        }
        __syncthreads();   // sync B: hfrag stores done CTA-wide

        if (tid == 0) {
            st_rel(&FLAG(g * 64 + cg), base0 + (unsigned)t + 1u);
        }

        // row-major history store off the critical path (later kernels only)
        *reinterpret_cast<unsigned short*>(
            &hall[((size_t)(t * BB) + g * 32 + pw_b) * HH + j0 + pw_j]) = hb;
    }
}

// ---------------------------------------------------------------------------
// Output projection (unchanged)
// ---------------------------------------------------------------------------
__global__ void k_out(const __half* __restrict__ h2,
                      const float* __restrict__ wout,
                      const float* __restrict__ bout,
                      float* __restrict__ out)
{
    int wg = (blockIdx.x * blockDim.x + threadIdx.x) >> 5;
    int lane = threadIdx.x & 31;
    if (wg >= TB) return;
    int t = wg >> 6;     // / BB
    int b = wg & 63;
    const __half* hp = h2 + (size_t)wg * HH;
    float sum = 0.0f;
    #pragma unroll
    for (int i = 0; i < 4; i++) {
        int k = i * 256 + lane * 8;
        uint4 v = *reinterpret_cast<const uint4*>(&hp[k]);
        const __half* pv = reinterpret_cast<const __half*>(&v);
        float4 w0 = *reinterpret_cast<const float4*>(&wout[k]);
        float4 w1 = *reinterpret_cast<const float4*>(&wout[k + 4]);
        sum += __half2float(pv[0]) * w0.x + __half2float(pv[1]) * w0.y
             + __half2float(pv[2]) * w0.z + __half2float(pv[3]) * w0.w
             + __half2float(pv[4]) * w1.x + __half2float(pv[5]) * w1.y
             + __half2float(pv[6]) * w1.z + __half2float(pv[7]) * w1.w;
    }
    #pragma unroll
    for (int off = 16; off; off >>= 1) sum += __shfl_xor_sync(0xffffffffu, sum, off);
    if (lane == 0) out[(size_t)b * TT + t] = sum + bout[0];
}

// ---------------------------------------------------------------------------
// Launch. Stream order keeps k_lstm_rec (layer 0) at our launch index 3 (the
// ncu capture slot).
// ---------------------------------------------------------------------------
extern "C" void kernel_launch(void* const* d_in, const int* in_sizes, int n_in,
                              void* d_out, int out_size)
{
    const float* x     = (const float*)d_in[0];
    const float* w_ih0 = (const float*)d_in[1];
    const float* w_hh0 = (const float*)d_in[2];
    const float* b_ih0 = (const float*)d_in[3];
    const float* b_hh0 = (const float*)d_in[4];
    const float* w_ih1 = (const float*)d_in[5];
    const float* w_hh1 = (const float*)d_in[6];
    const float* b_ih1 = (const float*)d_in[7];
    const float* b_hh1 = (const float*)d_in[8];
    const float* w_out = (const float*)d_in[9];
    const float* b_out = (const float*)d_in[10];
    float* out = (float*)d_out;

    void *p_xb, *p_wih0, *p_whh0, *p_wih1, *p_whh1, *p_gx, *p_h1, *p_h2;
    cudaGetSymbolAddress(&p_xb, d_xb);
    cudaGetSymbolAddress(&p_wih0, d_wih0);
    cudaGetSymbolAddress(&p_whh0, d_whh0);
    cudaGetSymbolAddress(&p_wih1, d_wih1);
    cudaGetSymbolAddress(&p_whh1, d_whh1);
    cudaGetSymbolAddress(&p_gx, d_gx);
    cudaGetSymbolAddress(&p_h1, d_h1);
    cudaGetSymbolAddress(&p_h2, d_h2);

    const int SMEM_REC  = 64 * HS * 2 + 8 * PB * 4;               // 132096 + 69632 = 201728 B
    const int SMEM_GEMM = (2 * BM * KP + 2 * BN * KP) * 2;        // 73728 B
    cudaFuncSetAttribute(k_lstm_rec, cudaFuncAttributeMaxDynamicSharedMemorySize, SMEM_REC);
    cudaFuncSetAttribute(k_gemm_bias, cudaFuncAttributeMaxDynamicSharedMemorySize, SMEM_GEMM);

    // idx 0: x conversion
    k_conv_x<<<(TB * INS) / 256, 256>>>(x, (__half*)p_xb);
    // idx 1: all weight conversions fused
    k_conv_w<<<(G4 * HH) / 256, 256>>>(w_ih0, (__half*)p_wih0, G4 * INS,
                                       w_hh0, (__half*)p_whh0, G4 * HH,
                                       w_ih1, (__half*)p_wih1, G4 * HH,
                                       w_hh1, (__half*)p_whh1, G4 * HH);

    dim3 gg(TB / BM, G4 / BN);

    // idx 2: gx0 = x @ w_ih0^T + biases (gate-interleaved output)
    k_gemm_bias<<<gg, 256, SMEM_GEMM>>>((__half*)p_xb, (__half*)p_wih0,
                                        b_ih0, b_hh0, (float*)p_gx, TB, G4, INS);
    // idx 3: layer-0 recurrence  (ncu capture target)
    k_lstm_rec<<<NCTA_REC, REC_THREADS, SMEM_REC>>>((float*)p_gx, (__half*)p_whh0,
                                                    (__half*)p_h1);

    // idx 4: gx1 = h1 @ w_ih1^T + biases ; idx 5: layer-1 recurrence
    k_gemm_bias<<<gg, 256, SMEM_GEMM>>>((__half*)p_h1, (__half*)p_wih1,
                                        b_ih1, b_hh1, (float*)p_gx, TB, G4, HH);
    k_lstm_rec<<<NCTA_REC, REC_THREADS, SMEM_REC>>>((float*)p_gx, (__half*)p_whh1,
                                                    (__half*)p_h2);

    // idx 6: output projection
    k_out<<<(TB * 32) / 256, 256>>>((__half*)p_h2, w_out, b_out, out);
}